// round 9
// baseline (speedup 1.0000x reference)
#include <cuda_runtime.h>
#include <cuda_bf16.h>
#include <cstdint>

#define BSZ 512
#define DIM 128
#define MARGIN 0.2f
#define APB 4                 // anchors per block
#define NBLK (BSZ / APB)      // 128 blocks
#define TJ 64                 // j-rows per tile
#define NT (BSZ / TJ)         // 8 tiles

// Scratch (no allocations anywhere)
__device__ float g_psum[BSZ];
__device__ int   g_pcnt[BSZ];
__device__ int   g_ctr;       // zero-init; last block resets -> replay-safe

typedef unsigned long long ull;

// ---- packed f32x2 helpers (Blackwell) -------------------------------------
__device__ __forceinline__ ull add2(ull a, ull b) {
    ull r; asm("add.rn.f32x2 %0, %1, %2;" : "=l"(r) : "l"(a), "l"(b)); return r;
}
__device__ __forceinline__ ull fma2(ull a, ull b, ull c) {
    ull r; asm("fma.rn.f32x2 %0, %1, %2, %3;" : "=l"(r) : "l"(a), "l"(b), "l"(c)); return r;
}
__device__ __forceinline__ float sum2(ull v) {
    float lo, hi;
    asm("mov.b64 {%0, %1}, %2;" : "=f"(lo), "=f"(hi) : "l"(v));
    return lo + hi;
}

// ---------------------------------------------------------------------------
// ONE fused kernel.
//  Phase 1: 4 distance rows per block, j tiled by 64 through smem (coalesced
//           LDG staging; packed f32x2 diff/fma; matches reference
//           sum((a-b)^2) then sqrt-if-positive).
//  Phase 2: warp-per-row mining (ballot masks, shuffle prefix for neg-rank,
//           warp-uniform early-exit window scan; reference quirks kept).
//  Phase 3: atomic-counter last-block deterministic finalize.
// ---------------------------------------------------------------------------
__global__ __launch_bounds__(256, 1)
void fused_kernel(const float* __restrict__ emb,
                  const int* __restrict__ labels,
                  float* __restrict__ out) {
    __shared__ __align__(16) ull   sB[TJ][65];     // tile rows (pad->2-way max)
    __shared__ __align__(16) float sAA[APB][DIM];  // NEGATED anchor rows
    __shared__ __align__(16) float sd[APB][BSZ];   // distance rows
    __shared__ int sLast;

    const int tid  = threadIdx.x;
    const int warp = tid >> 5;
    const int lane = tid & 31;
    const int i0   = blockIdx.x * APB;

    // ---- stage negated anchors (4 rows x 32 float4; threads 0..127) ----
    if (tid < 128) {
        const int a  = tid >> 5;
        const int d4 = tid & 31;
        const float4 v = *(const float4*)(emb + (size_t)(i0 + a) * DIM + d4 * 4);
        *(float4*)&sAA[a][d4 * 4] = make_float4(-v.x, -v.y, -v.z, -v.w);
    }

    // ---- phase 1: thread owns (a = tid>>6, jl = tid&63) per tile ----
    const int a  = tid >> 6;
    const int jl = tid & 63;
    const ull* arow = (const ull*)sAA[a];

    for (int t = 0; t < NT; t++) {
        const int t0 = t * TJ;
        // coalesced stage: 64 rows x 32 float4 = 2048; 8 per thread
        #pragma unroll
        for (int k = 0; k < 8; k++) {
            const int idx = tid + 256 * k;
            const int r   = idx >> 5;
            const int c4  = idx & 31;
            const float4 g = *(const float4*)(emb + (size_t)(t0 + r) * DIM + c4 * 4);
            float2* rowp = (float2*)sB[r];
            rowp[2 * c4 + 0] = make_float2(g.x, g.y);
            rowp[2 * c4 + 1] = make_float2(g.z, g.w);
        }
        __syncthreads();

        const ull* brow = sB[jl];
        ull acc0 = 0ull, acc1 = 0ull;          // 2 accs: break dep chain
        #pragma unroll 16
        for (int d2 = 0; d2 < 64; d2 += 2) {
            ull u = add2(brow[d2 + 0], arow[d2 + 0]);
            acc0 = fma2(u, u, acc0);
            ull v = add2(brow[d2 + 1], arow[d2 + 1]);
            acc1 = fma2(v, v, acc1);
        }
        const float s = sum2(acc0) + sum2(acc1);
        sd[a][t0 + jl] = s > 0.f ? sqrtf(s) : 0.f;
        __syncthreads();
    }

    // ---- phase 2: warps 0..3 mine row i = i0 + warp ----
    if (warp < APB) {
        const int w = warp;
        const int i = i0 + w;
        const int li = __ldg(labels + i);

        // neg ballot words; lane q holds word q
        unsigned myneg = 0;
        #pragma unroll
        for (int q = 0; q < 16; q++) {
            const int lab = __ldg(labels + q * 32 + lane);
            const unsigned b = __ballot_sync(0xffffffffu, lab != li);
            if (lane == q) myneg = b;
        }

        // positive & (p>i) words; valid-pair count
        unsigned myposgt = 0;
        if (lane < 16) {
            const int r = i - lane * 32;
            const unsigned gt = (r < 0) ? 0xffffffffu
                              : (r >= 31 ? 0u : (0xffffffffu << (r + 1)));
            myposgt = (~myneg) & gt;
        }
        const int cnt = __reduce_add_sync(0xffffffffu,
                                          (lane < 16) ? __popc(myposgt) : 0);

        // exclusive prefix of per-word negative counts (shuffle scan)
        int spf;
        {
            const int nc = (lane < 16) ? __popc(myneg) : 0;
            int incl = nc;
            #pragma unroll
            for (int d = 1; d < 16; d <<= 1) {
                const int tt = __shfl_up_sync(0xffffffffu, incl, d);
                if (lane >= d) incl += tt;
            }
            spf = incl - nc;
        }

        // fallback j0 = first negative index (argmax over all-False == 0)
        int j0 = 0;
        {
            const unsigned negany =
                __ballot_sync(0xffffffffu, lane < 16 && myneg != 0);
            if (negany) {
                const int c0 = __ffs(negany) - 1;
                const unsigned w0 = __shfl_sync(0xffffffffu, myneg, c0);
                j0 = c0 * 32 + (__ffs(w0) - 1);
            }
        }
        const float dfb = sd[w][j0];

        unsigned pmask16 = __ballot_sync(0xffffffffu, lane < 16 && myposgt != 0);

        float psum = 0.f;
        while (pmask16) {                 // words containing positives
            const int c = __ffs(pmask16) - 1;
            pmask16 &= pmask16 - 1;
            unsigned pm = __shfl_sync(0xffffffffu, myposgt, c);  // uniform
            while (pm) {
                const int b = __ffs(pm) - 1;
                pm &= pm - 1;
                const int p = c * 32 + b;
                const float dap = sd[w][p];
                const float hi  = dap + MARGIN;
                int minj = -1;
                #pragma unroll 1
                for (int q = 0; q < 16; q++) {     // warp-uniform early exit
                    const unsigned nw = __shfl_sync(0xffffffffu, myneg, q);
                    const float dj = sd[w][q * 32 + lane];
                    const bool hit = ((nw >> lane) & 1u) && dj > dap && dj < hi;
                    const unsigned bm = __ballot_sync(0xffffffffu, hit);
                    if (bm) { minj = q * 32 + (__ffs(bm) - 1); break; }
                }
                float dan;
                if (minj >= 0) {
                    const int mc = minj >> 5, mb = minj & 31;
                    const int base = __shfl_sync(0xffffffffu, spf, mc);
                    const unsigned nw = __shfl_sync(0xffffffffu, myneg, mc);
                    const int rank = base + __popc(nw & ((1u << mb) - 1u));
                    dan = sd[w][rank];    // reference quirk: index by neg-rank
                } else {
                    dan = dfb;
                }
                const float v = fmaf(dap, dap, MARGIN) - dan * dan;
                psum += v > 0.f ? v : 0.f;   // uniform across lanes
            }
        }

        if (lane == 0) {
            g_psum[i] = psum;
            g_pcnt[i] = cnt;
            __threadfence();
        }
    }
    __syncthreads();

    // ---- phase 3: last-block deterministic finalize ----
    if (tid == 0) {
        const int prev = atomicAdd(&g_ctr, 1);
        sLast = (prev == NBLK - 1) ? 1 : 0;
    }
    __syncthreads();

    if (sLast) {
        __threadfence();
        __shared__ float rs[256];
        __shared__ int   rc[256];
        rs[tid] = g_psum[tid] + g_psum[tid + 256];
        rc[tid] = g_pcnt[tid] + g_pcnt[tid + 256];
        __syncthreads();
        #pragma unroll
        for (int s = 128; s > 0; s >>= 1) {
            if (tid < s) { rs[tid] += rs[tid + s]; rc[tid] += rc[tid + s]; }
            __syncthreads();
        }
        if (tid == 0) {
            out[0] = rs[0] / (float)rc[0];
            g_ctr  = 0;                    // reset for next graph replay
        }
    }
}

// ---------------------------------------------------------------------------
extern "C" void kernel_launch(void* const* d_in, const int* in_sizes, int n_in,
                              void* d_out, int out_size) {
    const float* emb    = (const float*)d_in[0];
    const int*   labels = (const int*)d_in[1];
    float*       out    = (float*)d_out;

    fused_kernel<<<NBLK, 256>>>(emb, labels, out);
}

// round 11
// speedup vs baseline: 1.0280x; 1.0280x over previous
#include <cuda_runtime.h>
#include <cuda_bf16.h>
#include <cstdint>

#define BSZ 512
#define DIM 128
#define MARGIN 0.2f
#define APB 4                 // anchors per block
#define NBLK (BSZ / APB)      // 128 blocks
#define TJ 64                 // j-rows per tile
#define NT (BSZ / TJ)         // 8 tiles
#define SB_STRIDE 66          // ull per sB row (528 B): rows stagger across banks
#define SA_STRIDE 132         // floats per sAA row (528 B): anchors stagger too
#define SD_STRIDE 520         // floats per sd row: 4-lane same-j stores conflict-free

// Scratch (no allocations anywhere)
__device__ float g_psum[BSZ];
__device__ int   g_pcnt[BSZ];
__device__ int   g_ctr;       // zero-init; last block resets -> replay-safe

typedef unsigned long long ull;

// ---- packed f32x2 helpers (Blackwell) -------------------------------------
__device__ __forceinline__ ull add2(ull a, ull b) {
    ull r; asm("add.rn.f32x2 %0, %1, %2;" : "=l"(r) : "l"(a), "l"(b)); return r;
}
__device__ __forceinline__ ull fma2(ull a, ull b, ull c) {
    ull r; asm("fma.rn.f32x2 %0, %1, %2, %3;" : "=l"(r) : "l"(a), "l"(b), "l"(c)); return r;
}
__device__ __forceinline__ float sum2(ull v) {
    float lo, hi;
    asm("mov.b64 {%0, %1}, %2;" : "=f"(lo), "=f"(hi) : "l"(v));
    return lo + hi;
}

// ---------------------------------------------------------------------------
// ONE fused kernel.
//  Phase 1: 4 distance rows per block; j tiled by 64 through smem. Thread
//           (a = tid&3, j = tid>>2): lane quads broadcast-share the B row;
//           both operands bank-staggered -> 1 crossbar phase per LDS.128.
//           Packed f32x2 diff/fma = reference sum((a-b)^2), sqrt-if-positive.
//           Full DIM covered: 32 x ulonglong2 = 512 B = 128 floats.
//  Phase 2: warp-per-row mining (ballot masks, shuffle prefix neg-rank,
//           warp-uniform early-exit window scan; reference quirks kept).
//  Phase 3: atomic-counter last-block deterministic finalize.
// ---------------------------------------------------------------------------
__global__ __launch_bounds__(256, 1)
void fused_kernel(const float* __restrict__ emb,
                  const int* __restrict__ labels,
                  float* __restrict__ out) {
    __shared__ __align__(16) ull   sB[TJ][SB_STRIDE];      // 33.8 KB tile
    __shared__ __align__(16) float sAA[APB][SA_STRIDE];    // NEGATED anchors
    __shared__ __align__(16) float sd[APB][SD_STRIDE];     // distance rows
    __shared__ int sLast;

    const int tid  = threadIdx.x;
    const int warp = tid >> 5;
    const int lane = tid & 31;
    const int i0   = blockIdx.x * APB;

    // ---- stage negated anchors (4 rows x 32 float4; threads 0..127) ----
    if (tid < 128) {
        const int a  = tid >> 5;
        const int d4 = tid & 31;
        const float4 v = *(const float4*)(emb + (size_t)(i0 + a) * DIM + d4 * 4);
        *(float4*)&sAA[a][d4 * 4] = make_float4(-v.x, -v.y, -v.z, -v.w);
    }

    const int aIdx = tid & 3;
    const int jt   = tid >> 2;
    const ulonglong2* arow2 = (const ulonglong2*)sAA[aIdx];
    const ulonglong2* brow2 = (const ulonglong2*)sB[jt];

    for (int t = 0; t < NT; t++) {
        const int t0 = t * TJ;
        __syncthreads();   // previous compute done (and anchors staged, t=0)

        // stage 64 rows x 32 float4 = 2048; 8 per thread, coalesced
        #pragma unroll
        for (int k = 0; k < 8; k++) {
            const int idx = tid + 256 * k;
            const int r   = idx >> 5;
            const int c4  = idx & 31;
            const float4 g = *(const float4*)(emb + (size_t)(t0 + r) * DIM + c4 * 4);
            float2* rowp = (float2*)sB[r];
            rowp[2 * c4 + 0] = make_float2(g.x, g.y);
            rowp[2 * c4 + 1] = make_float2(g.z, g.w);
        }
        __syncthreads();

        ull acc0 = 0ull, acc1 = 0ull;          // 2 accs: break dep chain
        #pragma unroll
        for (int d4 = 0; d4 < 32; d4++) {      // 32 x 16 B = full 128 dims
            const ulonglong2 b  = brow2[d4];   // quad-broadcast, 1 phase
            const ulonglong2 av = arow2[d4];   // staggered, 1 phase
            ull u = add2(b.x, av.x);
            acc0 = fma2(u, u, acc0);
            ull v = add2(b.y, av.y);
            acc1 = fma2(v, v, acc1);
        }
        const float s = sum2(acc0) + sum2(acc1);
        sd[aIdx][t0 + jt] = s > 0.f ? sqrtf(s) : 0.f;
    }
    __syncthreads();

    // ---- phase 2: warps 0..3 mine row i = i0 + warp ----
    if (warp < APB) {
        const int w = warp;
        const int i = i0 + w;
        const int li = __ldg(labels + i);

        // neg ballot words; lane q holds word q
        unsigned myneg = 0;
        #pragma unroll
        for (int q = 0; q < 16; q++) {
            const int lab = __ldg(labels + q * 32 + lane);
            const unsigned b = __ballot_sync(0xffffffffu, lab != li);
            if (lane == q) myneg = b;
        }

        // positive & (p>i) words; valid-pair count
        unsigned myposgt = 0;
        if (lane < 16) {
            const int r = i - lane * 32;
            const unsigned gt = (r < 0) ? 0xffffffffu
                              : (r >= 31 ? 0u : (0xffffffffu << (r + 1)));
            myposgt = (~myneg) & gt;
        }
        const int cnt = __reduce_add_sync(0xffffffffu,
                                          (lane < 16) ? __popc(myposgt) : 0);

        // exclusive prefix of per-word negative counts (shuffle scan)
        int spf;
        {
            const int nc = (lane < 16) ? __popc(myneg) : 0;
            int incl = nc;
            #pragma unroll
            for (int d = 1; d < 16; d <<= 1) {
                const int tt = __shfl_up_sync(0xffffffffu, incl, d);
                if (lane >= d) incl += tt;
            }
            spf = incl - nc;
        }

        // fallback j0 = first negative index (argmax over all-False == 0)
        int j0 = 0;
        {
            const unsigned negany =
                __ballot_sync(0xffffffffu, lane < 16 && myneg != 0);
            if (negany) {
                const int c0 = __ffs(negany) - 1;
                const unsigned w0 = __shfl_sync(0xffffffffu, myneg, c0);
                j0 = c0 * 32 + (__ffs(w0) - 1);
            }
        }
        const float dfb = sd[w][j0];

        unsigned pmask16 = __ballot_sync(0xffffffffu, lane < 16 && myposgt != 0);

        float psum = 0.f;
        while (pmask16) {                 // words containing positives
            const int c = __ffs(pmask16) - 1;
            pmask16 &= pmask16 - 1;
            unsigned pm = __shfl_sync(0xffffffffu, myposgt, c);  // uniform
            while (pm) {
                const int b = __ffs(pm) - 1;
                pm &= pm - 1;
                const int p = c * 32 + b;
                const float dap = sd[w][p];
                const float hi  = dap + MARGIN;
                int minj = -1;
                #pragma unroll 1
                for (int q = 0; q < 16; q++) {     // warp-uniform early exit
                    const unsigned nw = __shfl_sync(0xffffffffu, myneg, q);
                    const float dj = sd[w][q * 32 + lane];
                    const bool hit = ((nw >> lane) & 1u) && dj > dap && dj < hi;
                    const unsigned bm = __ballot_sync(0xffffffffu, hit);
                    if (bm) { minj = q * 32 + (__ffs(bm) - 1); break; }
                }
                float dan;
                if (minj >= 0) {
                    const int mc = minj >> 5, mb = minj & 31;
                    const int base = __shfl_sync(0xffffffffu, spf, mc);
                    const unsigned nw = __shfl_sync(0xffffffffu, myneg, mc);
                    const int rank = base + __popc(nw & ((1u << mb) - 1u));
                    dan = sd[w][rank];    // reference quirk: index by neg-rank
                } else {
                    dan = dfb;
                }
                const float v = fmaf(dap, dap, MARGIN) - dan * dan;
                psum += v > 0.f ? v : 0.f;   // uniform across lanes
            }
        }

        if (lane == 0) {
            g_psum[i] = psum;
            g_pcnt[i] = cnt;
            __threadfence();
        }
    }
    __syncthreads();

    // ---- phase 3: last-block deterministic finalize ----
    if (tid == 0) {
        const int prev = atomicAdd(&g_ctr, 1);
        sLast = (prev == NBLK - 1) ? 1 : 0;
    }
    __syncthreads();

    if (sLast) {
        __threadfence();
        __shared__ float rs[256];
        __shared__ int   rc[256];
        rs[tid] = g_psum[tid] + g_psum[tid + 256];
        rc[tid] = g_pcnt[tid] + g_pcnt[tid + 256];
        __syncthreads();
        #pragma unroll
        for (int s = 128; s > 0; s >>= 1) {
            if (tid < s) { rs[tid] += rs[tid + s]; rc[tid] += rc[tid + s]; }
            __syncthreads();
        }
        if (tid == 0) {
            out[0] = rs[0] / (float)rc[0];
            g_ctr  = 0;                    // reset for next graph replay
        }
    }
}

// ---------------------------------------------------------------------------
extern "C" void kernel_launch(void* const* d_in, const int* in_sizes, int n_in,
                              void* d_out, int out_size) {
    const float* emb    = (const float*)d_in[0];
    const int*   labels = (const int*)d_in[1];
    float*       out    = (float*)d_out;

    fused_kernel<<<NBLK, 256>>>(emb, labels, out);
}